// round 12
// baseline (speedup 1.0000x reference)
#include <cuda_runtime.h>
#include <cuda_bf16.h>
#include <math.h>

// Problem constants (fixed by the dataset)
#define BB 8
#define NN 2000
#define CC 81
#define IOU_THR 0.5f
#define CLASS_OFFSET 100000.0f
#define CAP 96                  // per-(batch,class) bucket capacity (mean ~25, +14 sigma)
#define NROWS (BB * NN)         // 16000
#define NTASK (BB * (CC - 1))   // 640 NMS tasks

// Output layout: concat of reference's 7-tuple, all float32
// (nms_reg, nms_cls, rcnn_reg_adj, probs, reg_out, cls_out, keep)
#define OFF0 0
#define OFF1 (BB*NN*4)
#define OFF2 (OFF1 + BB*NN*2)
#define OFF3 (OFF2 + BB*NN*4)
#define OFF4 (OFF3 + BB*NN*CC)
#define OFF5 (OFF4 + BB*NN*4)
#define OFF6 (OFF5 + BB*NN*CC)

// ---- scratch (device globals; zero-initialized at module load; no allocation) ----
__device__ int                g_cnt[BB*CC];          // bucket counters; nms resets after reading
__device__ unsigned long long g_bkey[BB*CC*CAP];     // composite keys per bucket
__device__ float4             g_bbox[BB*CC*CAP];     // offset boxes per bucket (same slot as key)

// reduction input may arrive as int32 or float32; handle both.
__device__ __forceinline__ float read_reduction(const void* p) {
    if (p == nullptr) return 16.0f;
    int iv = *(const int*)p;
    if (iv > 0 && iv < (1 << 20)) return (float)iv;
    return *(const float*)p;
}

// ============================================================
// Kernel 1: direct prep, one warp per FOUR rows (ILP x4).
// Same per-row op sequence as every passing round; 4 independent
// row-chains interleave to hide SHFL/LDG latency. Triggers PDL
// completion so nms can pre-launch and park.
// ============================================================
#define PREP_TPB 256
#define PREP_BLOCKS (NROWS / 4 * 32 / PREP_TPB)   // 500

__global__ __launch_bounds__(PREP_TPB)
void prep_kernel(const float* __restrict__ nms_reg,
                 const float* __restrict__ nms_cls,
                 const float* __restrict__ rcnn_reg,
                 const float* __restrict__ rcnn_cls,
                 const void* __restrict__ redp,
                 float* __restrict__ out)
{
    const int gw   = (blockIdx.x * blockDim.x + threadIdx.x) >> 5;
    const int lane = threadIdx.x & 31;
    const int row0 = gw * 4;
    if (row0 >= NROWS) { cudaTriggerProgrammaticLaunchCompletion(); return; }

    const bool has2 = (lane < CC - 64);

    // ---- 12 independent loads in flight ----
    float v0[4], v1[4], v2[4];
    #pragma unroll
    for (int rr = 0; rr < 4; rr++) {
        const float* cl = rcnn_cls + (size_t)(row0 + rr) * CC;
        v0[rr] = cl[lane];
        v1[rr] = cl[lane + 32];
        v2[rr] = has2 ? cl[lane + 64] : -INFINITY;
    }

    // ---- 4 interleaved max trees ----
    float m[4];
    #pragma unroll
    for (int rr = 0; rr < 4; rr++) m[rr] = fmaxf(v0[rr], fmaxf(v1[rr], v2[rr]));
    #pragma unroll
    for (int o = 16; o; o >>= 1) {
        #pragma unroll
        for (int rr = 0; rr < 4; rr++)
            m[rr] = fmaxf(m[rr], __shfl_xor_sync(0xFFFFFFFFu, m[rr], o));
    }

    // ---- exp + 4 interleaved sum trees ----
    float e0[4], e1[4], e2[4], s[4];
    #pragma unroll
    for (int rr = 0; rr < 4; rr++) {
        e0[rr] = expf(v0[rr] - m[rr]);
        e1[rr] = expf(v1[rr] - m[rr]);
        e2[rr] = has2 ? expf(v2[rr] - m[rr]) : 0.0f;
        s[rr] = e0[rr] + e1[rr] + e2[rr];
    }
    #pragma unroll
    for (int o = 16; o; o >>= 1) {
        #pragma unroll
        for (int rr = 0; rr < 4; rr++)
            s[rr] += __shfl_xor_sync(0xFFFFFFFFu, s[rr], o);
    }

    // ---- probs + stores + 4 interleaved argmax trees ----
    float p0[4], p1[4], p2[4];
    float bp[4]; int bi[4];
    #pragma unroll
    for (int rr = 0; rr < 4; rr++) {
        p0[rr] = e0[rr] / s[rr];
        p1[rr] = e1[rr] / s[rr];
        p2[rr] = e2[rr] / s[rr];
        float* po = out + OFF3 + (size_t)(row0 + rr) * CC;
        po[lane]      = p0[rr];
        po[lane + 32] = p1[rr];
        if (has2) po[lane + 64] = p2[rr];

        float b = p0[rr]; int i = lane;
        if (p1[rr] > b) { b = p1[rr]; i = lane + 32; }
        if (has2 && p2[rr] > b) { b = p2[rr]; i = lane + 64; }
        bp[rr] = b; bi[rr] = i;
    }
    #pragma unroll
    for (int o = 16; o; o >>= 1) {
        #pragma unroll
        for (int rr = 0; rr < 4; rr++) {
            float op = __shfl_xor_sync(0xFFFFFFFFu, bp[rr], o);
            int   oi = __shfl_xor_sync(0xFFFFFFFFu, bi[rr], o);
            if (op > bp[rr] || (op == bp[rr] && oi < bi[rr])) { bp[rr] = op; bi[rr] = oi; }
        }
    }

    // ---- speculative cls_out = probs * k ----
    float kk[4];
    #pragma unroll
    for (int rr = 0; rr < 4; rr++) {
        kk[rr] = (bi[rr] != 0) ? 1.0f : 0.0f;
        float* co = out + OFF5 + (size_t)(row0 + rr) * CC;
        co[lane]      = p0[rr] * kk[rr];
        co[lane + 32] = p1[rr] * kk[rr];
        if (has2) co[lane + 64] = p2[rr] * kk[rr];
    }

    // ---- scalar tail: lanes 0..3, one row each ----
    if (lane < 4) {
        const float bpl = (lane == 0) ? bp[0] : (lane == 1) ? bp[1] : (lane == 2) ? bp[2] : bp[3];
        const int   cls = (lane == 0) ? bi[0] : (lane == 1) ? bi[1] : (lane == 2) ? bi[2] : bi[3];
        const float k   = (cls != 0) ? 1.0f : 0.0f;
        const int   row = row0 + lane;
        const float red = read_reduction(redp);

        float4 nr = ((const float4*)nms_reg)[row];
        float rt = floorf(nr.x * red) / red;
        float rl = floorf(nr.y * red) / red;
        float rb = ceilf(nr.z * red) / red;
        float rw = ceilf(nr.w * red) / red;

        float4 rg = ((const float4*)rcnn_reg)[row];
        float4 adj;
        adj.x = rg.x + rt; adj.y = rg.y + rl; adj.z = rg.z + rb; adj.w = rg.w + rw;
        ((float4*)(out + OFF2))[row] = adj;

        float4 ro;
        ro.x = adj.x * k; ro.y = adj.y * k; ro.z = adj.z * k; ro.w = adj.w * k;
        ((float4*)(out + OFF4))[row] = ro;

        ((float4*)(out + OFF0))[row] = nr;
        ((float2*)(out + OFF1))[row] = ((const float2*)nms_cls)[row];

        out[OFF6 + row] = k;

        if (cls != 0) {
            unsigned sb = __float_as_uint(bpl);
            unsigned so = (sb & 0x80000000u) ? ~sb : (sb | 0x80000000u);
            unsigned sdesc = ~so;
            int b = row / NN, n = row % NN;
            unsigned long long key = ((unsigned long long)sdesc << 32)
                                   | (unsigned long long)(unsigned)n;
            int bc = b * CC + cls;
            int pos = atomicAdd(&g_cnt[bc], 1);
            if (pos < CAP) {
                size_t slot = (size_t)bc * CAP + pos;
                g_bkey[slot] = key;
                float off = (float)cls * CLASS_OFFSET;
                float4 ob;
                ob.x = adj.x + off; ob.y = adj.y + off;
                ob.z = adj.z + off; ob.w = adj.w + off;
                g_bbox[slot] = ob;
            }
        }
    }

    // allow the dependent NMS kernel to start launching
    cudaTriggerProgrammaticLaunchCompletion();
}

// ============================================================
// Kernel 2: block-per-task bitmask NMS, 128 threads (4 warps).
// Same algorithm as R10; smaller blocks ramp faster.
// ============================================================
#define NTPB 128
__global__ __launch_bounds__(NTPB)
void nms_kernel(float* __restrict__ out)
{
    const int task = blockIdx.x;                 // 0..639
    const int tid  = threadIdx.x;
    const int lane = tid & 31;
    const int wid  = tid >> 5;                   // 0..3

    const int b  = task / (CC - 1);
    const int c  = task % (CC - 1) + 1;
    const int bc = b * CC + c;

    __shared__ unsigned long long s_key[CAP];
    __shared__ float4             s_box[CAP];
    __shared__ unsigned short     s_sid[CAP];
    __shared__ uint4              s_rm [CAP];
    __shared__ unsigned           s_active[3];

    cudaGridDependencySynchronize();

    const size_t base = (size_t)bc * CAP;
    unsigned long long mykey = 0ull;
    float4 mybox;
    if (tid < CAP) {
        mykey = __ldcg(&g_bkey[base + tid]);
        mybox = __ldcg(&g_bbox[base + tid]);
    }
    int n = __ldcg(&g_cnt[bc]);
    if (n > CAP) n = CAP;

    if (tid < 3) s_active[tid] = 0u;
    if (tid < n) s_key[tid] = mykey;
    __syncthreads();
    if (tid == 0) g_cnt[bc] = 0;                 // reset for next replay

    if (n <= 0) return;

    // rank sort + box placement (keys unique via idx low bits)
    if (tid < n) {
        int rank = 0;
        for (int kk = 0; kk < n; kk++) rank += (s_key[kk] < mykey);
        s_sid[rank] = (unsigned short)(mykey & 0xFFFFFFFFu);
        s_box[rank] = mybox;
    }
    __syncthreads();

    // ---- Phase B: suppression matrix, rows split across 4 warps ----
    {
        float4 bx0, bx1, bx2;
        float ar0 = 0.0f, ar1 = 0.0f, ar2 = 0.0f;
        if (lane < n)      { bx0 = s_box[lane];      ar0 = (bx0.z - bx0.x) * (bx0.w - bx0.y); }
        if (lane + 32 < n) { bx1 = s_box[lane + 32]; ar1 = (bx1.z - bx1.x) * (bx1.w - bx1.y); }
        if (lane + 64 < n) { bx2 = s_box[lane + 64]; ar2 = (bx2.z - bx2.x) * (bx2.w - bx2.y); }

        for (int i = wid; i < n - 1; i += NTPB / 32) {
            float4 bi = s_box[i];
            float areai = (bi.z - bi.x) * (bi.w - bi.y);

            bool sup0 = false, sup1 = false, sup2 = false;
            {
                int j = lane;
                if (j < n && j > i) {
                    float it = fmaxf(bi.x, bx0.x);
                    float il = fmaxf(bi.y, bx0.y);
                    float ib = fminf(bi.z, bx0.z);
                    float ir = fminf(bi.w, bx0.w);
                    float inter = fmaxf(ib - it, 0.0f) * fmaxf(ir - il, 0.0f);
                    float uni = areai + ar0 - inter;
                    float iou = inter / fmaxf(uni, 1e-9f);
                    sup0 = (iou > IOU_THR);
                }
            }
            unsigned w0 = __ballot_sync(0xFFFFFFFFu, sup0);
            unsigned w1 = 0, w2 = 0;
            if (n > 32) {
                int j = lane + 32;
                if (j < n && j > i) {
                    float it = fmaxf(bi.x, bx1.x);
                    float il = fmaxf(bi.y, bx1.y);
                    float ib = fminf(bi.z, bx1.z);
                    float ir = fminf(bi.w, bx1.w);
                    float inter = fmaxf(ib - it, 0.0f) * fmaxf(ir - il, 0.0f);
                    float uni = areai + ar1 - inter;
                    float iou = inter / fmaxf(uni, 1e-9f);
                    sup1 = (iou > IOU_THR);
                }
                w1 = __ballot_sync(0xFFFFFFFFu, sup1);
            }
            if (n > 64) {
                int j = lane + 64;
                if (j < n && j > i) {
                    float it = fmaxf(bi.x, bx2.x);
                    float il = fmaxf(bi.y, bx2.y);
                    float ib = fminf(bi.z, bx2.z);
                    float ir = fminf(bi.w, bx2.w);
                    float inter = fmaxf(ib - it, 0.0f) * fmaxf(ir - il, 0.0f);
                    float uni = areai + ar2 - inter;
                    float iou = inter / fmaxf(uni, 1e-9f);
                    sup2 = (iou > IOU_THR);
                }
                w2 = __ballot_sync(0xFFFFFFFFu, sup2);
            }
            if (lane == 0) {
                uint4 rm; rm.x = w0; rm.y = w1; rm.z = w2; rm.w = 0;
                s_rm[i] = rm;
                if ((w0 | w1 | w2) != 0u)
                    atomicOr(&s_active[i >> 5], 1u << (i & 31));
            }
        }
    }
    __syncthreads();

    // ---- Phase C: ffs-scan over ACTIVE rows only (every warp, registers) ----
    unsigned a0 = s_active[0], a1 = s_active[1], a2 = s_active[2];
    if ((a0 | a1 | a2) == 0u) return;    // no suppression anywhere: outputs final

    unsigned k0, k1, k2;
    k0 = (n >= 32) ? 0xFFFFFFFFu : ((1u << n) - 1u);
    k1 = (n >= 64) ? 0xFFFFFFFFu : ((n > 32) ? ((1u << (n - 32)) - 1u) : 0u);
    k2 = (n > 64) ? ((n >= 96) ? 0xFFFFFFFFu : ((1u << (n - 64)) - 1u)) : 0u;

    for (;;) {
        unsigned c0 = a0 & k0, c1 = a1 & k1, c2 = a2 & k2;
        int i;
        if (c0)      i = __ffs(c0) - 1;
        else if (c1) i = 31 + __ffs(c1);
        else if (c2) i = 63 + __ffs(c2);
        else break;
        uint4 rm = s_rm[i];                      // smem broadcast (read-only)
        k0 &= ~rm.x; k1 &= ~rm.y; k2 &= ~rm.z;
        if (i < 32)      a0 &= ~(1u << i);
        else if (i < 64) a1 &= ~(1u << (i - 32));
        else             a2 &= ~(1u << (i - 64));
    }
    // rm[i] has only bits > i set, so ascending ffs order reproduces the
    // reference greedy order exactly; rows with rm==0 never change keep state.

    // ---- Phase D: fixup suppressed rows, split across warps ----
    for (int i = wid; i < n; i += NTPB / 32) {
        unsigned word = (i < 32) ? k0 : ((i < 64) ? k1 : k2);
        if (!((word >> (i & 31)) & 1u)) {
            int row = b * NN + (int)s_sid[i];
            float* co = out + OFF5 + (size_t)row * CC;
            co[lane]      = 0.0f;
            co[lane + 32] = 0.0f;
            if (lane < CC - 64) co[lane + 64] = 0.0f;
            if (lane == 0) {
                float4 z; z.x = 0.0f; z.y = 0.0f; z.z = 0.0f; z.w = 0.0f;
                ((float4*)(out + OFF4))[row] = z;
                out[OFF6 + row] = 0.0f;
            }
        }
    }
}

extern "C" void kernel_launch(void* const* d_in, const int* in_sizes, int n_in,
                              void* d_out, int out_size)
{
    const float* nms_reg  = (const float*)d_in[0];
    const float* nms_cls  = (const float*)d_in[1];
    const float* rcnn_reg = (const float*)d_in[2];
    const float* rcnn_cls = (const float*)d_in[3];
    const void*  redp     = (n_in >= 5) ? d_in[4] : nullptr;
    float* out = (float*)d_out;
    (void)in_sizes; (void)out_size;

    prep_kernel<<<PREP_BLOCKS, PREP_TPB>>>(nms_reg, nms_cls, rcnn_reg, rcnn_cls, redp, out);

    // NMS with programmatic dependent launch: pre-launches and parks,
    // hiding launch/distribution latency behind prep's execution.
    cudaLaunchConfig_t cfg = {};
    cfg.gridDim  = dim3(NTASK, 1, 1);
    cfg.blockDim = dim3(NTPB, 1, 1);
    cfg.dynamicSmemBytes = 0;
    cudaLaunchAttribute attrs[1];
    attrs[0].id = cudaLaunchAttributeProgrammaticStreamSerialization;
    attrs[0].val.programmaticStreamSerializationAllowed = 1;
    cfg.attrs = attrs;
    cfg.numAttrs = 1;
    cudaLaunchKernelEx(&cfg, nms_kernel, out);
}